// round 14
// baseline (speedup 1.0000x reference)
#include <cuda_runtime.h>
#include <cstdint>

// Lightning attention, chunked-parallel, mma.sync tf32 (row.col), cp.async fills.
//   K1: C_j = (k*k_decay)^T @ v   (2048 CTAs, 64x128x128, inline cvt+scale, 2 CTAs/SM)
//   KF: fused scan+output. 128 CTAs = 32 bh x 4 t-blocks; each walks its bh's 32
//       chunks in order carrying state S in smem (S = lamB*S + C_j, C streamed).
//       Causal skip: t-block tblk needs only K/V rows < 32*(tblk+1); out-GEMM
//       k-loop truncated likewise. No g_S, no scan kernel (-192 MB traffic).

#define SD  136   // smem row stride (words): 136%32==8 -> conflict-free frag loads
#define SDK 72    // K1's 64-col k tile stride (72%32==8)

__device__ float g_C[1024u * 16384u];   // 64 MB: chunk KV products

__device__ __forceinline__ uint32_t f2tf(float x){
    uint32_t r; asm("cvt.rna.tf32.f32 %0, %1;" : "=r"(r) : "f"(x)); return r;
}
__device__ __forceinline__ uint32_t s2u(const void* p){
    uint32_t a;
    asm("{ .reg .u64 t; cvta.to.shared.u64 t, %1; cvt.u32.u64 %0, t; }" : "=r"(a) : "l"(p));
    return a;
}
__device__ __forceinline__ void cpa16(uint32_t dst, const void* src){
    asm volatile("cp.async.cg.shared.global [%0], [%1], 16;" :: "r"(dst), "l"(src));
}
#define CP_COMMIT() asm volatile("cp.async.commit_group;" ::: "memory")
#define CP_WAIT0()  asm volatile("cp.async.wait_group 0;" ::: "memory")
#define CP_WAIT1()  asm volatile("cp.async.wait_group 1;" ::: "memory")

__device__ __forceinline__ void mma8(float* c, const uint32_t* a, const uint32_t* b){
    asm volatile(
        "mma.sync.aligned.m16n8k8.row.col.f32.tf32.tf32.f32 "
        "{%0,%1,%2,%3}, {%4,%5,%6,%7}, {%8,%9}, {%0,%1,%2,%3};"
        : "+f"(c[0]), "+f"(c[1]), "+f"(c[2]), "+f"(c[3])
        : "r"(a[0]), "r"(a[1]), "r"(a[2]), "r"(a[3]), "r"(b[0]), "r"(b[1]));
}

// K1 warp GEMM: 32(m) x 32(n) x 128. A transposed-indexed + per-k scale + cvt; B natural + cvt.
__device__ __forceinline__ void gemm_k1(const float* __restrict__ A, int sa,
                                        const float* __restrict__ B, int sb,
                                        const float* __restrict__ kd,
                                        float acc[2][4][4], int rb, int cb, int lane){
    const int lr = lane >> 2, lc = lane & 3;
#pragma unroll
    for (int ks = 0; ks < 16; ks++){
        const int kc = ks * 8 + lc;
        const float s0 = kd[kc], s4 = kd[kc + 4];
        uint32_t a[2][4];
#pragma unroll
        for (int mt = 0; mt < 2; mt++){
            const int m = rb + mt * 16 + lr;
            a[mt][0] = f2tf(A[kc * sa + m] * s0);
            a[mt][1] = f2tf(A[kc * sa + m + 8] * s0);
            a[mt][2] = f2tf(A[(kc + 4) * sa + m] * s4);
            a[mt][3] = f2tf(A[(kc + 4) * sa + m + 8] * s4);
        }
#pragma unroll
        for (int nt = 0; nt < 4; nt++){
            const int n = cb + nt * 8 + lr;
            uint32_t b[2] = { f2tf(B[kc * sb + n]), f2tf(B[(kc + 4) * sb + n]) };
            mma8(acc[0][nt], a[0], b);
            mma8(acc[1][nt], a[1], b);
        }
    }
}

// KF warp GEMM: 16(m) x 16(n) x (8*ksteps). CVTA/CVTB: fp32->tf32 inline; else raw bits.
// BT: element (k,n) at B[n*sb+k].
template<bool CVTA, bool BT, bool CVTB>
__device__ __forceinline__ void gemm16(const float* __restrict__ A, int sa,
                                       const float* __restrict__ B, int sb,
                                       float acc[2][4], int rb, int cb, int lane, int ksteps){
    const int lr = lane >> 2, lc = lane & 3;
#pragma unroll 4
    for (int ks = 0; ks < ksteps; ks++){
        const int kc = ks * 8 + lc;
        const int m = rb + lr;
        float a0 = A[m * sa + kc],     a1 = A[(m + 8) * sa + kc];
        float a2 = A[m * sa + kc + 4], a3 = A[(m + 8) * sa + kc + 4];
        uint32_t a[4];
        if (CVTA){ a[0]=f2tf(a0); a[1]=f2tf(a1); a[2]=f2tf(a2); a[3]=f2tf(a3); }
        else { a[0]=__float_as_uint(a0); a[1]=__float_as_uint(a1);
               a[2]=__float_as_uint(a2); a[3]=__float_as_uint(a3); }
#pragma unroll
        for (int nt = 0; nt < 2; nt++){
            const int n = cb + nt * 8 + lr;
            float b0v, b1v;
            if (BT){ b0v = B[n * sb + kc];  b1v = B[n * sb + kc + 4]; }
            else   { b0v = B[kc * sb + n];  b1v = B[(kc + 4) * sb + n]; }
            uint32_t b[2];
            if (CVTB){ b[0] = f2tf(b0v);            b[1] = f2tf(b1v); }
            else     { b[0] = __float_as_uint(b0v); b[1] = __float_as_uint(b1v); }
            mma8(acc[nt], a, b);
        }
    }
}

__device__ __forceinline__ void fill_tile(uint32_t sdst, const float* gsrc, int gstride_f,
                                          int rowbytes, int sstride_b, int rows,
                                          int tid, int nthr){
    const int cpr = rowbytes >> 4;
    const int total = rows * cpr;
    for (int i = tid; i < total; i += nthr){
        int r = i / cpr, c = i - r * cpr;
        cpa16(sdst + r * sstride_b + c * 16, (const char*)gsrc + (size_t)r * gstride_f * 4 + c * 16);
    }
}

// ---------------- K1: C_j = (k * k_decay)^T @ v  (half of d-rows per CTA) ----------------
__global__ void __launch_bounds__(256) k_chunkKV(const float* __restrict__ k,
                                                 const float* __restrict__ v,
                                                 const float* __restrict__ s){
    extern __shared__ float sm[];
    float* kd  = sm;
    float* ksm = sm + 128;
    float* vsm = ksm + 128 * SDK;
    const int tid = threadIdx.x, w = tid >> 5, lane = tid & 31;
    const int g = blockIdx.x >> 1, dh = blockIdx.x & 1, bh = g >> 5;
    const float sh = __ldg(&s[bh & 15]);
    const size_t base = ((size_t)bh * 4096 + (size_t)(g & 31) * 128) * 128;
    const uint32_t sb = s2u(sm);

    fill_tile(sb + 128 * 4, k + base + dh * 64, 128, 256, SDK * 4, 128, tid, 256);
    fill_tile(sb + (128 + 128 * SDK) * 4, v + base, 128, 512, SD * 4, 128, tid, 256);
    CP_COMMIT();
    if (tid < 128) kd[tid] = __expf(-sh * (float)(128 - tid));
    CP_WAIT0();
    __syncthreads();

    const int rb = (w & 1) * 32, cb = (w >> 1) * 32;
    float acc[2][4][4] = {};
    gemm_k1(ksm, SDK, vsm, SD, kd, acc, rb, cb, lane);

    float* C = g_C + (size_t)g * 16384 + (size_t)dh * 64 * 128;
    const int lr = lane >> 2, lc2 = (lane & 3) * 2;
#pragma unroll
    for (int mt = 0; mt < 2; mt++){
        const int r = rb + mt * 16 + lr;
#pragma unroll
        for (int nt = 0; nt < 4; nt++){
            const int c = cb + nt * 8 + lc2;
            *(float2*)(C + (size_t)r * 128 + c)       = make_float2(acc[mt][nt][0], acc[mt][nt][1]);
            *(float2*)(C + (size_t)(r + 8) * 128 + c) = make_float2(acc[mt][nt][2], acc[mt][nt][3]);
        }
    }
}

// ---------------- KF: fused scan + output ----------------
__global__ void __launch_bounds__(512) k_fused(const float* __restrict__ q,
                                               const float* __restrict__ k,
                                               const float* __restrict__ v,
                                               const float* __restrict__ s,
                                               float* __restrict__ o){
    extern __shared__ float sm[];
    float* dec = sm;                     // 128 decay values for this head
    float* Qb  = sm + 128;               // 32 x SD   (Q tile, fp32)
    float* Sb  = Qb + 32 * SD;           // 128 x SD  (carried state, fp32)
    float* Kb  = Sb + 128 * SD;          // 128 x SD  (K fp32; then scores tf32 rows 0..31)
    float* Vb  = Kb + 128 * SD;          // 128 x SD  (V fp32)
    const int tid = threadIdx.x, w = tid >> 5, lane = tid & 31;
    const int bh = blockIdx.x >> 2, tblk = blockIdx.x & 3;
    const int rows_kv = (tblk + 1) * 32;         // causal: only K/V rows i < rows_kv matter
    const int ksteps_out = (tblk + 1) * 4;
    const float sh = __ldg(&s[bh & 15]);
    const float lamB = __expf(-sh * 128.0f);
    const size_t base_bh = (size_t)bh * 4096 * 128;
    const uint32_t sb = s2u(sm);
    const uint32_t oQ = sb + 128 * 4;
    const uint32_t oK = oQ + 32 * SD * 4 + 128 * SD * 4;    // skip over Sb
    const uint32_t oV = oK + 128 * SD * 4;

    const int rb = (w >> 3) * 16, cb = (w & 7) * 16;
    const int lr = lane >> 2, lc2 = (lane & 3) * 2;
    const int r0 = rb + lr, r8 = rb + 8 + lr;               // CTA-local t rows
    const int tg0 = tblk * 32 + r0, tg8 = tblk * 32 + r8;   // global t within chunk

    if (tid < 128) dec[tid] = __expf(-sh * (float)tid);
    for (int i = tid; i < 128 * SD; i += 512) Sb[i] = 0.0f;

    // prologue: chunk-0 fills.  group order (steady invariant: {Q, KV} in flight)
    fill_tile(oQ, q + base_bh + (size_t)tblk * 4096, 128, 512, SD * 4, 32, tid, 512);
    CP_COMMIT();                                             // {Q0}
    fill_tile(oK, k + base_bh, 128, 512, SD * 4, rows_kv, tid, 512);
    fill_tile(oV, v + base_bh, 128, 512, SD * 4, rows_kv, tid, 512);
    CP_COMMIT();                                             // {Q0, KV0}

    for (int j = 0; j < 32; j++){
        const size_t coff = ((size_t)bh * 32 + j) * 16384;
        const size_t base = base_bh + (size_t)j * 16384;

        // C prefetch into registers (consumed at S-update)
        const float4* Cp = (const float4*)(g_C + coff);
        float4 cr[8];
#pragma unroll
        for (int p = 0; p < 8; p++) cr[p] = Cp[tid + p * 512];

        CP_WAIT1();                  // Q_j landed (KV_j may still fly)
        __syncthreads();             // Q visible; prev S-update done

        // inter = Q_j @ S, pre-scaled by q_decay  -> shared accumulator with out
        float acc_o[2][4] = {};
        gemm16<true, false, true>(Qb, SD, Sb, SD, acc_o, rb, cb, lane, 16);
        {
            const float e0 = dec[tg0], e8 = dec[tg8];
#pragma unroll
            for (int nt = 0; nt < 2; nt++){
                acc_o[nt][0] *= e0; acc_o[nt][1] *= e0;
                acc_o[nt][2] *= e8; acc_o[nt][3] *= e8;
            }
        }

        CP_WAIT0();                  // K_j, V_j landed
        __syncthreads();             // visible to all

        // scores = Q_j @ K^T (warps whose columns are fully masked skip)
        float acc_s[2][4] = {};
        if (cb < rows_kv)
            gemm16<true, true, true>(Qb, SD, Kb, SD, acc_s, rb, cb, lane, 16);
        __syncthreads();             // all reads of Qb, Kb complete

        // Q_{j+1} prefetch (Qb free); lands under out-GEMM
        if (j < 31)
            fill_tile(oQ, q + base_bh + (size_t)(j + 1) * 16384 + (size_t)tblk * 4096,
                      128, 512, SD * 4, 32, tid, 512);
        CP_COMMIT();                 // {Q'}

        // epilogue: mask + decay -> write tf32 scores into Kb rows 0..31
        if (cb < rows_kv){
            uint32_t* sc = (uint32_t*)Kb;
#pragma unroll
            for (int nt = 0; nt < 2; nt++){
                const int c = cb + nt * 8 + lc2;
                uint32_t v00 = f2tf((tg0 >= c    ) ? acc_s[nt][0] * dec[tg0 - c]     : 0.0f);
                uint32_t v01 = f2tf((tg0 >= c + 1) ? acc_s[nt][1] * dec[tg0 - c - 1] : 0.0f);
                uint32_t v10 = f2tf((tg8 >= c    ) ? acc_s[nt][2] * dec[tg8 - c]     : 0.0f);
                uint32_t v11 = f2tf((tg8 >= c + 1) ? acc_s[nt][3] * dec[tg8 - c - 1] : 0.0f);
                *(uint2*)(sc + r0 * SD + c) = make_uint2(v00, v01);
                *(uint2*)(sc + r8 * SD + c) = make_uint2(v10, v11);
            }
        }
        __syncthreads();             // scores visible

        // out = inter + scores @ V  (k-loop truncated by causality)
        gemm16<false, false, true>(Kb, SD, Vb, SD, acc_o, rb, cb, lane, ksteps_out);
        __syncthreads();             // Kb (scores), Vb reads complete

        // K_{j+1}, V_{j+1} fills; land under S-update + o-store + next inter
        if (j < 31){
            fill_tile(oK, k + base + 16384, 128, 512, SD * 4, rows_kv, tid, 512);
            fill_tile(oV, v + base + 16384, 128, 512, SD * 4, rows_kv, tid, 512);
        }
        CP_COMMIT();                 // {Q', KV'}

        // S update: S = lamB * S + C_j
#pragma unroll
        for (int p = 0; p < 8; p++){
            const int e = (tid + p * 512) << 2;
            float* sp = Sb + (e >> 7) * SD + (e & 127);
            float4 sv = *(float4*)sp;
            sv.x = lamB * sv.x + cr[p].x;
            sv.y = lamB * sv.y + cr[p].y;
            sv.z = lamB * sv.z + cr[p].z;
            sv.w = lamB * sv.w + cr[p].w;
            *(float4*)sp = sv;
        }

        // o store
        float* O = o + base + (size_t)tblk * 4096;
#pragma unroll
        for (int nt = 0; nt < 2; nt++){
            const int c = cb + nt * 8 + lc2;
            *(float2*)(O + r0 * 128 + c) = make_float2(acc_o[nt][0], acc_o[nt][1]);
            *(float2*)(O + r8 * 128 + c) = make_float2(acc_o[nt][2], acc_o[nt][3]);
        }
    }
}

extern "C" void kernel_launch(void* const* d_in, const int* in_sizes, int n_in,
                              void* d_out, int out_size) {
    const float* q = (const float*)d_in[0];
    const float* k = (const float*)d_in[1];
    const float* v = (const float*)d_in[2];
    const float* s = (const float*)d_in[3];
    float* o = (float*)d_out;

    const int sm1 = (128 + 128 * SDK + 128 * SD) * 4;          // 107,008 B (2 CTAs/SM)
    const int smF = (128 + 32 * SD + 3 * 128 * SD) * 4;        // 226,816 B (1 CTA/SM)
    cudaFuncSetAttribute(k_chunkKV, cudaFuncAttributeMaxDynamicSharedMemorySize, sm1);
    cudaFuncSetAttribute(k_fused,   cudaFuncAttributeMaxDynamicSharedMemorySize, smF);

    k_chunkKV<<<2048, 256, sm1>>>(k, v, s);
    k_fused<<<128, 512, smF>>>(q, k, v, s, o);
}

// round 15
// speedup vs baseline: 1.7784x; 1.7784x over previous
#include <cuda_runtime.h>
#include <cstdint>

// Lightning attention, chunked-parallel, mma.sync tf32 (row.col), cp.async fills.
//   K1: C_j = (k*k_decay)^T @ v   (2048 CTAs, 64x128x128, inline cvt+scale, 2 CTAs/SM)
//   K2: exclusive decayed prefix scan g_C -> g_S (pure streams, float4, prefetch-2;
//       S stored tf32)
//   K3: persistent (grid=148), cross-chunk pipelined: next-Q prefetch under GEMM3,
//       next-S/K fills under o-store; per-head decay tables precomputed in smem.

#define SD  136   // smem row stride (words) for 128-col tiles (136%32==8, conflict-free)
#define SDK 72    // smem row stride for K1's 64-col k tile    (72%32==8)
#define GRIDN 148

__device__ float g_C[1024u * 16384u];   // 64 MB: chunk KV products
__device__ float g_S[1024u * 16384u];   // 64 MB: scanned exclusive states (tf32 bits)

__device__ __forceinline__ uint32_t f2tf(float x){
    uint32_t r; asm("cvt.rna.tf32.f32 %0, %1;" : "=r"(r) : "f"(x)); return r;
}
__device__ __forceinline__ uint32_t s2u(const void* p){
    uint32_t a;
    asm("{ .reg .u64 t; cvta.to.shared.u64 t, %1; cvt.u32.u64 %0, t; }" : "=r"(a) : "l"(p));
    return a;
}
__device__ __forceinline__ void cpa16(uint32_t dst, const void* src){
    asm volatile("cp.async.cg.shared.global [%0], [%1], 16;" :: "r"(dst), "l"(src));
}
#define CP_COMMIT() asm volatile("cp.async.commit_group;" ::: "memory")
#define CP_WAIT0()  asm volatile("cp.async.wait_group 0;" ::: "memory")
#define CP_WAIT1()  asm volatile("cp.async.wait_group 1;" ::: "memory")

__device__ __forceinline__ void mma8(float* c, const uint32_t* a, const uint32_t* b){
    asm volatile(
        "mma.sync.aligned.m16n8k8.row.col.f32.tf32.tf32.f32 "
        "{%0,%1,%2,%3}, {%4,%5,%6,%7}, {%8,%9}, {%0,%1,%2,%3};"
        : "+f"(c[0]), "+f"(c[1]), "+f"(c[2]), "+f"(c[3])
        : "r"(a[0]), "r"(a[1]), "r"(a[2]), "r"(a[3]), "r"(b[0]), "r"(b[1]));
}

// K1 warp GEMM: 32(m) x 32(n) x 128. A transposed-indexed + per-k scale + cvt; B natural + cvt.
__device__ __forceinline__ void gemm_k1(const float* __restrict__ A, int sa,
                                        const float* __restrict__ B, int sb,
                                        const float* __restrict__ kd,
                                        float acc[2][4][4], int rb, int cb, int lane){
    const int lr = lane >> 2, lc = lane & 3;
#pragma unroll
    for (int ks = 0; ks < 16; ks++){
        const int kc = ks * 8 + lc;
        const float s0 = kd[kc], s4 = kd[kc + 4];
        uint32_t a[2][4];
#pragma unroll
        for (int mt = 0; mt < 2; mt++){
            const int m = rb + mt * 16 + lr;
            a[mt][0] = f2tf(A[kc * sa + m] * s0);
            a[mt][1] = f2tf(A[kc * sa + m + 8] * s0);
            a[mt][2] = f2tf(A[(kc + 4) * sa + m] * s4);
            a[mt][3] = f2tf(A[(kc + 4) * sa + m + 8] * s4);
        }
#pragma unroll
        for (int nt = 0; nt < 4; nt++){
            const int n = cb + nt * 8 + lr;
            uint32_t b[2] = { f2tf(B[kc * sb + n]), f2tf(B[(kc + 4) * sb + n]) };
            mma8(acc[0][nt], a[0], b);
            mma8(acc[1][nt], a[1], b);
        }
    }
}

// K3 warp GEMM: 32x32x128. CVTA/CVTB: operand is fp32, convert inline; else raw tf32 bits.
// BT: element (k,n) at B[n*sb+k].
template<bool CVTA, bool BT, bool CVTB>
__device__ __forceinline__ void gemm_k3(const float* __restrict__ A, int sa,
                                        const float* __restrict__ B, int sb,
                                        float acc[2][4][4], int rb, int cb, int lane){
    const int lr = lane >> 2, lc = lane & 3;
#pragma unroll
    for (int ks = 0; ks < 16; ks++){
        const int kc = ks * 8 + lc;
        uint32_t a[2][4];
#pragma unroll
        for (int mt = 0; mt < 2; mt++){
            const int m = rb + mt * 16 + lr;
            float a0 = A[m * sa + kc],     a1 = A[(m + 8) * sa + kc];
            float a2 = A[m * sa + kc + 4], a3 = A[(m + 8) * sa + kc + 4];
            if (CVTA){
                a[mt][0] = f2tf(a0); a[mt][1] = f2tf(a1);
                a[mt][2] = f2tf(a2); a[mt][3] = f2tf(a3);
            } else {
                a[mt][0] = __float_as_uint(a0); a[mt][1] = __float_as_uint(a1);
                a[mt][2] = __float_as_uint(a2); a[mt][3] = __float_as_uint(a3);
            }
        }
#pragma unroll
        for (int nt = 0; nt < 4; nt++){
            const int n = cb + nt * 8 + lr;
            float b0v, b1v;
            if (BT){ b0v = B[n * sb + kc];  b1v = B[n * sb + kc + 4]; }
            else   { b0v = B[kc * sb + n];  b1v = B[(kc + 4) * sb + n]; }
            uint32_t b[2];
            if (CVTB){ b[0] = f2tf(b0v);             b[1] = f2tf(b1v); }
            else     { b[0] = __float_as_uint(b0v);  b[1] = __float_as_uint(b1v); }
            mma8(acc[0][nt], a[0], b);
            mma8(acc[1][nt], a[1], b);
        }
    }
}

__device__ __forceinline__ void fill_tile(uint32_t sdst, const float* gsrc, int gstride_f,
                                          int rowbytes, int sstride_b, int rows,
                                          int tid, int nthr){
    const int cpr = rowbytes >> 4;
    const int total = rows * cpr;
    for (int i = tid; i < total; i += nthr){
        int r = i / cpr, c = i - r * cpr;
        cpa16(sdst + r * sstride_b + c * 16, (const char*)gsrc + (size_t)r * gstride_f * 4 + c * 16);
    }
}

// ---------------- K1: C_j = (k * k_decay)^T @ v  (half of d-rows per CTA) ----------------
__global__ void __launch_bounds__(256) k_chunkKV(const float* __restrict__ k,
                                                 const float* __restrict__ v,
                                                 const float* __restrict__ s){
    extern __shared__ float sm[];
    float* kd  = sm;                    // 128 floats
    float* ksm = sm + 128;              // [tau][d-half], SDK stride
    float* vsm = ksm + 128 * SDK;       // [tau][e], SD stride
    const int tid = threadIdx.x, w = tid >> 5, lane = tid & 31;
    const int g = blockIdx.x >> 1, dh = blockIdx.x & 1, bh = g >> 5;
    const float sh = __ldg(&s[bh & 15]);
    const size_t base = ((size_t)bh * 4096 + (size_t)(g & 31) * 128) * 128;
    const uint32_t sb = s2u(sm);

    fill_tile(sb + 128 * 4, k + base + dh * 64, 128, 256, SDK * 4, 128, tid, 256);
    fill_tile(sb + (128 + 128 * SDK) * 4, v + base, 128, 512, SD * 4, 128, tid, 256);
    CP_COMMIT();
    if (tid < 128) kd[tid] = __expf(-sh * (float)(128 - tid));
    CP_WAIT0();
    __syncthreads();

    const int rb = (w & 1) * 32, cb = (w >> 1) * 32;
    float acc[2][4][4] = {};
    gemm_k1(ksm, SDK, vsm, SD, kd, acc, rb, cb, lane);

    float* C = g_C + (size_t)g * 16384 + (size_t)dh * 64 * 128;
    const int lr = lane >> 2, lc2 = (lane & 3) * 2;
#pragma unroll
    for (int mt = 0; mt < 2; mt++){
        const int r = rb + mt * 16 + lr;
#pragma unroll
        for (int nt = 0; nt < 4; nt++){
            const int c = cb + nt * 8 + lc2;
            *(float2*)(C + (size_t)r * 128 + c)       = make_float2(acc[mt][nt][0], acc[mt][nt][1]);
            *(float2*)(C + (size_t)(r + 8) * 128 + c) = make_float2(acc[mt][nt][2], acc[mt][nt][3]);
        }
    }
}

// ---------------- K2: exclusive decayed prefix scan, g_C -> g_S (tf32 out) ----------------
__global__ void __launch_bounds__(256) k_scan(const float* __restrict__ s){
    const int bh = blockIdx.y;
    const int e4 = blockIdx.x * 256 + threadIdx.x;
    const float lamB = __expf(-__ldg(&s[bh & 15]) * 128.0f);
    const float4* __restrict__ src = (const float4*)(g_C + (size_t)bh * 32 * 16384) + e4;
    uint4* __restrict__ dst        = (uint4*)(g_S + (size_t)bh * 32 * 16384) + e4;

    float4 val = make_float4(0.f, 0.f, 0.f, 0.f);
    float4 c0 = src[0];
    float4 c1 = src[4096];
#pragma unroll
    for (int j = 0; j < 32; j++){
        float4 cn = (j < 30) ? src[(j + 2) * 4096] : make_float4(0.f, 0.f, 0.f, 0.f);
        dst[j * 4096] = make_uint4(f2tf(val.x), f2tf(val.y), f2tf(val.z), f2tf(val.w));
        val.x = lamB * val.x + c0.x;
        val.y = lamB * val.y + c0.y;
        val.z = lamB * val.z + c0.z;
        val.w = lamB * val.w + c0.w;
        c0 = c1;
        c1 = cn;
    }
}

// ---------------- K3: persistent output, cross-chunk pipelined ----------------
__global__ void __launch_bounds__(512) k_output(const float* __restrict__ q,
                                                const float* __restrict__ k,
                                                const float* __restrict__ v,
                                                const float* __restrict__ s,
                                                float* __restrict__ o){
    extern __shared__ float sm[];
    float* decs = sm;                    // 16 heads x 128 decay values
    float* Qs   = sm + 2048;             // Q (fp32, cvt inline)
    float* buf1 = Qs + 128 * SD;         // K (fp32), later scores (tf32 bits)
    float* buf2 = buf1 + 128 * SD;       // S (tf32 bits), later V (fp32)
    const int tid = threadIdx.x, w = tid >> 5, lane = tid & 31;
    const uint32_t sb = s2u(sm);
    const uint32_t oQ = sb + 8192, o1 = oQ + 128 * SD * 4, o2 = o1 + 128 * SD * 4;
    const int rb = (w >> 2) * 32, cb = (w & 3) * 32;
    const int lr = lane >> 2, lc2 = (lane & 3) * 2;

    // per-head decay tables, once
    for (int i = tid; i < 2048; i += 512){
        int h = i >> 7, t = i & 127;
        decs[i] = __expf(-__ldg(&s[h]) * (float)t);
    }

    int g = blockIdx.x;
    if (g < 1024){
        const size_t b0 = ((size_t)(g >> 5) * 4096 + (size_t)(g & 31) * 128) * 128;
        fill_tile(oQ, q + b0, 128, 512, SD * 4, 128, tid, 512); CP_COMMIT();  // Q
        fill_tile(o2, g_S + (size_t)g * 16384, 128, 512, SD * 4, 128, tid, 512); CP_COMMIT(); // S
        fill_tile(o1, k + b0, 128, 512, SD * 4, 128, tid, 512); CP_COMMIT();  // K
    }

    for (; g < 1024; g += GRIDN){
        const int bh = g >> 5;
        const float* dec = decs + ((bh & 15) << 7);
        const size_t base = ((size_t)bh * 4096 + (size_t)(g & 31) * 128) * 128;
        const int gn = g + GRIDN;
        const size_t basen = (gn < 1024)
            ? ((size_t)(gn >> 5) * 4096 + (size_t)(gn & 31) * 128) * 128 : 0;

        CP_WAIT1();                 // Q + S arrived (K still in flight)
        __syncthreads();

        float acc2[2][4][4] = {};   // inter = Q @ S
        gemm_k3<true, false, false>(Qs, SD, buf2, SD, acc2, rb, cb, lane);

        CP_WAIT0();                 // K arrived
        __syncthreads();            // all warps done reading buf2 (S)

        fill_tile(o2, v + base, 128, 512, SD * 4, 128, tid, 512);
        CP_COMMIT();                // V (lands under GEMM1 + epilogue)

        float acc1[2][4][4] = {};   // scores = Q @ K^T
        gemm_k3<true, true, true>(Qs, SD, buf1, SD, acc1, rb, cb, lane);
        __syncthreads();            // done reading buf1 (K) and Qs (Q)

        // prefetch next chunk's Q into Qs (dead now); lands under epilogue+GEMM3
        if (gn < 1024) fill_tile(oQ, q + basen, 128, 512, SD * 4, 128, tid, 512);
        CP_COMMIT();                // nextQ

        // epilogue: mask+decay scores -> buf1 as tf32 bits; pre-scale inter by q_decay
        uint32_t* sc = (uint32_t*)buf1;
#pragma unroll
        for (int mt = 0; mt < 2; mt++){
            const int r = rb + mt * 16 + lr;
            const float e0 = dec[r], e8 = dec[r + 8];
#pragma unroll
            for (int nt = 0; nt < 4; nt++){
                const int c = cb + nt * 8 + lc2;
                uint32_t v00 = f2tf((r     >= c    ) ? acc1[mt][nt][0] * dec[r - c]     : 0.0f);
                uint32_t v01 = f2tf((r     >= c + 1) ? acc1[mt][nt][1] * dec[r - c - 1] : 0.0f);
                uint32_t v10 = f2tf((r + 8 >= c    ) ? acc1[mt][nt][2] * dec[r + 8 - c] : 0.0f);
                uint32_t v11 = f2tf((r + 8 >= c + 1) ? acc1[mt][nt][3] * dec[r + 7 - c] : 0.0f);
                *(uint2*)(sc + r * SD + c)       = make_uint2(v00, v01);
                *(uint2*)(sc + (r + 8) * SD + c) = make_uint2(v10, v11);
                acc2[mt][nt][0] *= e0; acc2[mt][nt][1] *= e0;
                acc2[mt][nt][2] *= e8; acc2[mt][nt][3] *= e8;
            }
        }

        CP_WAIT1();                 // V arrived (nextQ still in flight)
        __syncthreads();            // scores visible, V ready

        // out = qdec*(Q@S) + scores @ V
        gemm_k3<false, false, true>(buf1, SD, buf2, SD, acc2, rb, cb, lane);
        __syncthreads();            // all warps done with buf1 (scores), buf2 (V)

        // next chunk's S and K fills: overlap with o-store below
        if (gn < 1024) fill_tile(o2, g_S + (size_t)gn * 16384, 128, 512, SD * 4, 128, tid, 512);
        CP_COMMIT();                // nextS
        if (gn < 1024) fill_tile(o1, k + basen, 128, 512, SD * 4, 128, tid, 512);
        CP_COMMIT();                // nextK

#pragma unroll
        for (int mt = 0; mt < 2; mt++){
            const int r = rb + mt * 16 + lr;
#pragma unroll
            for (int nt = 0; nt < 4; nt++){
                const int c = cb + nt * 8 + lc2;
                *(float2*)(o + base + (size_t)r * 128 + c)       = make_float2(acc2[mt][nt][0], acc2[mt][nt][1]);
                *(float2*)(o + base + (size_t)(r + 8) * 128 + c) = make_float2(acc2[mt][nt][2], acc2[mt][nt][3]);
            }
        }
    }
}

extern "C" void kernel_launch(void* const* d_in, const int* in_sizes, int n_in,
                              void* d_out, int out_size) {
    const float* q = (const float*)d_in[0];
    const float* k = (const float*)d_in[1];
    const float* v = (const float*)d_in[2];
    const float* s = (const float*)d_in[3];
    float* o = (float*)d_out;

    const int sm1 = (128 + 128 * SDK + 128 * SD) * 4;       // 107,008 B  (2 CTAs/SM)
    const int sm3 = 8192 + 3 * 128 * SD * 4;                // 217,088 B
    cudaFuncSetAttribute(k_chunkKV, cudaFuncAttributeMaxDynamicSharedMemorySize, sm1);
    cudaFuncSetAttribute(k_output,  cudaFuncAttributeMaxDynamicSharedMemorySize, sm3);

    k_chunkKV<<<2048, 256, sm1>>>(k, v, s);
    k_scan<<<dim3(16, 32), 256>>>(s);
    k_output<<<GRIDN, 512, sm3>>>(q, k, v, s, o);
}